// round 2
// baseline (speedup 1.0000x reference)
#include <cuda_runtime.h>
#include <math.h>

#define BATCH 64
#define NPTS  1024
#define D16   256
#define D64   1024
#define D128  2048
#define DG    8192

// ---------------- scratch (no allocations allowed) ----------------
__device__ float g_x  [BATCH * NPTS];   // GCN output
__device__ float g_f  [BATCH * D16];    // relu(fl)
__device__ float g_i  [BATCH * D64];    // relu(il)
__device__ float g_z  [BATCH * D128];   // relu(ol) = z
__device__ float g_pre[BATCH * DG];     // z @ w_ih^T + b_ih + b_hh
__device__ float g_h  [2 * D128];       // double-buffered hidden state
__device__ float g_c  [D128];           // cell state

__global__ void init_kernel()
{
    int tid = blockIdx.x * blockDim.x + threadIdx.x;
    if (tid < D128) { g_h[tid] = 0.f; g_c[tid] = 0.f; }
}

// ---------------- GCN: one block per sample ----------------
__global__ void __launch_bounds__(1024) gcn_kernel(
    const float* __restrict__ in,
    const float* __restrict__ gc1_w, const float* __restrict__ gc1_b,
    const float* __restrict__ gc2_w, const float* __restrict__ gc2_b,
    float* __restrict__ out)
{
    __shared__ __align__(16) float xs[NPTS];
    __shared__ float s2[NPTS];
    int b = blockIdx.x, tid = threadIdx.x;
    xs[tid] = in[b * NPTS + tid];
    __syncthreads();
    float xi = xs[tid];

    // stable top-4 smallest |xi - xj| (strict <, ascending j => matches top_k tiebreak)
    float d0 = 1e30f, d1 = 1e30f, d2 = 1e30f, d3 = 1e30f;
    int   i0 = 0, i1 = 0, i2 = 0, i3 = 0;
    const float4* xs4 = (const float4*)xs;
    for (int j4 = 0; j4 < NPTS / 4; j4++) {
        float4 v = xs4[j4];
        int jb = j4 * 4;
#pragma unroll
        for (int c = 0; c < 4; c++) {
            int j = jb + c;
            float xv = (c == 0) ? v.x : (c == 1) ? v.y : (c == 2) ? v.z : v.w;
            float d = fabsf(xi - xv);
            if (j != tid && d < d3) {
                if (d < d2) {
                    d3 = d2; i3 = i2;
                    if (d < d1) {
                        d2 = d1; i2 = i1;
                        if (d < d0) { d1 = d0; i1 = i0; d0 = d; i0 = j; }
                        else        { d1 = d;  i1 = j; }
                    } else { d2 = d; i2 = j; }
                } else { d3 = d; i3 = j; }
            }
        }
    }

    float xsum = xs[i0] + xs[i1] + xs[i2] + xs[i3];
    float w0 = gc1_w[0], w1 = gc1_w[1], w2 = gc1_w[2], w3 = gc1_w[3];
    float b0 = gc1_b[0], b1 = gc1_b[1], b2 = gc1_b[2], b3 = gc1_b[3];
    float v0 = gc2_w[0], v1 = gc2_w[1], v2 = gc2_w[2], v3 = gc2_w[3];
    float s = fmaxf(fmaf(w0, xsum, b0), 0.f) * v0
            + fmaxf(fmaf(w1, xsum, b1), 0.f) * v1
            + fmaxf(fmaf(w2, xsum, b2), 0.f) * v2
            + fmaxf(fmaf(w3, xsum, b3), 0.f) * v3;
    s2[tid] = s;
    __syncthreads();
    out[b * NPTS + tid] = s2[i0] + s2[i1] + s2[i2] + s2[i3] + gc2_b[0];
}

// ---------------- small dense layers: block = (one sample row, 128 cols) ----------------
__global__ void mlp_small_kernel(const float* __restrict__ in, const float* __restrict__ w,
                                 const float* __restrict__ bias, float* __restrict__ out,
                                 int K, int N)
{
    __shared__ float4 xr4[256];      // up to K=1024
    float* xr = (float*)xr4;
    int m = blockIdx.x;
    int tid = threadIdx.x;
    for (int k = tid; k < K; k += 128) xr[k] = in[m * K + k];
    __syncthreads();
    int n = blockIdx.y * 128 + tid;
    const float4* wr = (const float4*)(w + (size_t)n * K);
    float ax = 0.f, ay = 0.f, az = 0.f, aw = 0.f;
    int K4 = K >> 2;
    for (int k4 = 0; k4 < K4; k4++) {
        float4 wv = wr[k4];
        float4 xv = xr4[k4];
        ax = fmaf(wv.x, xv.x, ax);
        ay = fmaf(wv.y, xv.y, ay);
        az = fmaf(wv.z, xv.z, az);
        aw = fmaf(wv.w, xv.w, aw);
    }
    out[m * N + n] = fmaxf((ax + ay) + (az + aw) + bias[n], 0.f);
}

// ---------------- big dense layers: 128 cols/block, MROWS rows/thread ----------------
template<int MROWS, int S>
__global__ void mlp_big_kernel(const float* __restrict__ in, const float* __restrict__ w,
                               const float* __restrict__ bias, const float* __restrict__ bias2,
                               float* __restrict__ out, int K, int N, int do_relu)
{
    __shared__ __align__(16) float xs[32 * S];
    int tid = threadIdx.x;
    int m0 = blockIdx.y * MROWS;
    int n = blockIdx.x * 128 + tid;
    float acc[MROWS];
#pragma unroll
    for (int m = 0; m < MROWS; m++) acc[m] = 0.f;
    const float* wrow = w + (size_t)n * K;

    for (int k0 = 0; k0 < K; k0 += 32) {
        __syncthreads();
        for (int l = tid; l < MROWS * 32; l += 128) {
            int kk = l & 31, m = l >> 5;
            xs[kk * S + m] = in[(size_t)(m0 + m) * K + k0 + kk];
        }
        __syncthreads();
#pragma unroll 1
        for (int kk4 = 0; kk4 < 8; kk4++) {
            float4 wv = *(const float4*)(wrow + k0 + kk4 * 4);
#pragma unroll
            for (int c = 0; c < 4; c++) {
                float wvc = (c == 0) ? wv.x : (c == 1) ? wv.y : (c == 2) ? wv.z : wv.w;
                const float4* xrow = (const float4*)(xs + (kk4 * 4 + c) * S);
#pragma unroll
                for (int mq = 0; mq < MROWS / 4; mq++) {
                    float4 xv = xrow[mq];
                    acc[4 * mq + 0] = fmaf(xv.x, wvc, acc[4 * mq + 0]);
                    acc[4 * mq + 1] = fmaf(xv.y, wvc, acc[4 * mq + 1]);
                    acc[4 * mq + 2] = fmaf(xv.z, wvc, acc[4 * mq + 2]);
                    acc[4 * mq + 3] = fmaf(xv.w, wvc, acc[4 * mq + 3]);
                }
            }
        }
    }
    float bb = bias[n] + (bias2 ? bias2[n] : 0.f);
#pragma unroll
    for (int m = 0; m < MROWS; m++) {
        float v = acc[m] + bb;
        out[(size_t)(m0 + m) * N + n] = do_relu ? fmaxf(v, 0.f) : v;
    }
}

// ---------------- LSTM: one kernel per timestep, no grid barrier ----------------
// Block b owns hidden units u in [b*16, b*16+16). It computes all 4 gate rows
// for those units (64 dot-products of length 2048), then does the pointwise
// c/h update locally and writes h to the other buffer of g_h. Deadlock-free.
__device__ __forceinline__ float sigmoidf_(float x) { return 1.f / (1.f + __expf(-x)); }
__device__ __forceinline__ float tanhf_(float x)    { float e = __expf(2.f * x); return 1.f - 2.f / (e + 1.f); }

__global__ void __launch_bounds__(1024) lstm_step_kernel(const float* __restrict__ whh,
                                                         float* __restrict__ out, int t)
{
    __shared__ __align__(16) float hs[D128];
    __shared__ float gbuf[64];
    int tid  = threadIdx.x;
    int warp = tid >> 5, lane = tid & 31;
    int u0 = blockIdx.x * 16;

    const float* hin = g_h + (t & 1) * D128;
    for (int k = tid; k < D128; k += 1024) hs[k] = hin[k];
    __syncthreads();

    const float4* h4 = (const float4*)hs;
    // 32 warps, 64 rows -> 2 rows per warp
#pragma unroll
    for (int p = 0; p < 2; p++) {
        int lr = warp * 2 + p;            // 0..63
        int gate = lr >> 4, uu = lr & 15;
        int row = gate * D128 + u0 + uu;
        const float4* wr = (const float4*)(whh + (size_t)row * D128);
        float sx = 0.f, sy = 0.f, sz = 0.f, sw = 0.f;
#pragma unroll
        for (int it = 0; it < 16; it++) {
            float4 wv = wr[it * 32 + lane];
            float4 hv = h4[it * 32 + lane];
            sx = fmaf(wv.x, hv.x, sx);
            sy = fmaf(wv.y, hv.y, sy);
            sz = fmaf(wv.z, hv.z, sz);
            sw = fmaf(wv.w, hv.w, sw);
        }
        float s = (sx + sy) + (sz + sw);
#pragma unroll
        for (int o = 16; o > 0; o >>= 1) s += __shfl_down_sync(0xffffffffu, s, o);
        if (lane == 0) gbuf[lr] = s + g_pre[t * DG + row];
    }
    __syncthreads();

    if (tid < 16) {
        int u = u0 + tid;
        float ig = gbuf[tid], fg = gbuf[16 + tid], gv = gbuf[32 + tid], og = gbuf[48 + tid];
        float c = sigmoidf_(fg) * g_c[u] + sigmoidf_(ig) * tanhf_(gv);
        float h = sigmoidf_(og) * tanhf_(c);
        g_c[u] = c;
        g_h[((t + 1) & 1) * D128 + u] = h;
        out[t * D128 + u] = h;
    }
}

// ---------------- launch ----------------
extern "C" void kernel_launch(void* const* d_in, const int* in_sizes, int n_in,
                              void* d_out, int out_size)
{
    const float* input = (const float*)d_in[0];
    const float* gc1_w = (const float*)d_in[3];
    const float* gc1_b = (const float*)d_in[4];
    const float* gc2_w = (const float*)d_in[5];
    const float* gc2_b = (const float*)d_in[6];
    const float* fl_w  = (const float*)d_in[7];
    const float* fl_b  = (const float*)d_in[8];
    const float* il_w  = (const float*)d_in[9];
    const float* il_b  = (const float*)d_in[10];
    const float* ol_w  = (const float*)d_in[11];
    const float* ol_b  = (const float*)d_in[12];
    const float* w_ih  = (const float*)d_in[13];
    const float* w_hh  = (const float*)d_in[14];
    const float* b_ih  = (const float*)d_in[15];
    const float* b_hh  = (const float*)d_in[16];
    float* out = (float*)d_out;

    static float *px = nullptr, *pf, *pi, *pz, *ppre;
    if (!px) {
        cudaGetSymbolAddress((void**)&px,   g_x);
        cudaGetSymbolAddress((void**)&pf,   g_f);
        cudaGetSymbolAddress((void**)&pi,   g_i);
        cudaGetSymbolAddress((void**)&pz,   g_z);
        cudaGetSymbolAddress((void**)&ppre, g_pre);
    }

    init_kernel<<<2, 1024>>>();
    gcn_kernel<<<BATCH, 1024>>>(input, gc1_w, gc1_b, gc2_w, gc2_b, px);
    // f = relu(x @ fl_w^T + fl_b)         (K=1024, N=256)
    mlp_small_kernel<<<dim3(BATCH, D16 / 128), 128>>>(px, fl_w, fl_b, pf, NPTS, D16);
    // i = relu(f @ il_w^T + il_b)         (K=256, N=1024)
    mlp_small_kernel<<<dim3(BATCH, D64 / 128), 128>>>(pf, il_w, il_b, pi, D16, D64);
    // z = relu(i @ ol_w^T + ol_b)         (K=1024, N=2048)
    mlp_big_kernel<4, 8><<<dim3(D128 / 128, BATCH / 4), 128>>>(pi, ol_w, ol_b, nullptr, pz, D64, D128, 1);
    // pre = z @ w_ih^T + b_ih + b_hh      (K=2048, N=8192)
    mlp_big_kernel<16, 24><<<dim3(DG / 128, BATCH / 16), 128>>>(pz, w_ih, b_ih, b_hh, ppre, D128, DG, 0);
    // LSTM scan: 64 sequential step kernels (graph-serialized)
    for (int t = 0; t < BATCH; t++)
        lstm_step_kernel<<<D128 / 16, 1024>>>(w_hh, out, t);
}

// round 3
// speedup vs baseline: 1.0387x; 1.0387x over previous
#include <cuda_runtime.h>
#include <cuda_fp16.h>
#include <math.h>

#define BATCH 64
#define NPTS  1024
#define D16   256
#define D64   1024
#define D128  2048
#define DG    8192

// ---------------- scratch (no allocations allowed) ----------------
__device__ float  g_x  [BATCH * NPTS];   // GCN output
__device__ float  g_f  [BATCH * D16];    // relu(fl)
__device__ float  g_i  [BATCH * D64];    // relu(il)
__device__ float  g_z  [BATCH * D128];   // relu(ol) = z
__device__ float  g_pre[BATCH * DG];     // z @ w_ih^T + b_ih + b_hh
__device__ float  g_h  [2 * D128];       // double-buffered hidden state
__device__ float  g_c  [D128];           // cell state
__device__ __half g_whh_h[4 * D128 * D128];  // fp16 copy of w_hh (33.5 MB)

__global__ void init_kernel()
{
    int tid = blockIdx.x * blockDim.x + threadIdx.x;
    if (tid < D128) { g_h[tid] = 0.f; g_c[tid] = 0.f; }
}

// ---------------- w_hh fp32 -> fp16 (runs every replay; deterministic) ----------------
__global__ void __launch_bounds__(256) convert_whh_kernel(const float* __restrict__ w,
                                                          __half* __restrict__ out)
{
    int i = (blockIdx.x * 256 + threadIdx.x) * 8;
    float4 a = *(const float4*)(w + i);
    float4 b = *(const float4*)(w + i + 4);
    __half2 h0 = __floats2half2_rn(a.x, a.y);
    __half2 h1 = __floats2half2_rn(a.z, a.w);
    __half2 h2 = __floats2half2_rn(b.x, b.y);
    __half2 h3 = __floats2half2_rn(b.z, b.w);
    uint4 p;
    p.x = *(unsigned*)&h0; p.y = *(unsigned*)&h1;
    p.z = *(unsigned*)&h2; p.w = *(unsigned*)&h3;
    *(uint4*)(out + i) = p;
}

// ---------------- GCN: one block per sample ----------------
__global__ void __launch_bounds__(1024) gcn_kernel(
    const float* __restrict__ in,
    const float* __restrict__ gc1_w, const float* __restrict__ gc1_b,
    const float* __restrict__ gc2_w, const float* __restrict__ gc2_b,
    float* __restrict__ out)
{
    __shared__ __align__(16) float xs[NPTS];
    __shared__ float s2[NPTS];
    int b = blockIdx.x, tid = threadIdx.x;
    xs[tid] = in[b * NPTS + tid];
    __syncthreads();
    float xi = xs[tid];

    // stable top-4 smallest |xi - xj| (strict <, ascending j => matches top_k tiebreak)
    float d0 = 1e30f, d1 = 1e30f, d2 = 1e30f, d3 = 1e30f;
    int   i0 = 0, i1 = 0, i2 = 0, i3 = 0;
    const float4* xs4 = (const float4*)xs;
    for (int j4 = 0; j4 < NPTS / 4; j4++) {
        float4 v = xs4[j4];
        int jb = j4 * 4;
#pragma unroll
        for (int c = 0; c < 4; c++) {
            int j = jb + c;
            float xv = (c == 0) ? v.x : (c == 1) ? v.y : (c == 2) ? v.z : v.w;
            float d = fabsf(xi - xv);
            if (j != tid && d < d3) {
                if (d < d2) {
                    d3 = d2; i3 = i2;
                    if (d < d1) {
                        d2 = d1; i2 = i1;
                        if (d < d0) { d1 = d0; i1 = i0; d0 = d; i0 = j; }
                        else        { d1 = d;  i1 = j; }
                    } else { d2 = d; i2 = j; }
                } else { d3 = d; i3 = j; }
            }
        }
    }

    float xsum = xs[i0] + xs[i1] + xs[i2] + xs[i3];
    float w0 = gc1_w[0], w1 = gc1_w[1], w2 = gc1_w[2], w3 = gc1_w[3];
    float b0 = gc1_b[0], b1 = gc1_b[1], b2 = gc1_b[2], b3 = gc1_b[3];
    float v0 = gc2_w[0], v1 = gc2_w[1], v2 = gc2_w[2], v3 = gc2_w[3];
    float s = fmaxf(fmaf(w0, xsum, b0), 0.f) * v0
            + fmaxf(fmaf(w1, xsum, b1), 0.f) * v1
            + fmaxf(fmaf(w2, xsum, b2), 0.f) * v2
            + fmaxf(fmaf(w3, xsum, b3), 0.f) * v3;
    s2[tid] = s;
    __syncthreads();
    out[b * NPTS + tid] = s2[i0] + s2[i1] + s2[i2] + s2[i3] + gc2_b[0];
}

// ---------------- small dense layers: block = (one sample row, 128 cols) ----------------
__global__ void mlp_small_kernel(const float* __restrict__ in, const float* __restrict__ w,
                                 const float* __restrict__ bias, float* __restrict__ out,
                                 int K, int N)
{
    __shared__ float4 xr4[256];      // up to K=1024
    float* xr = (float*)xr4;
    int m = blockIdx.x;
    int tid = threadIdx.x;
    for (int k = tid; k < K; k += 128) xr[k] = in[m * K + k];
    __syncthreads();
    int n = blockIdx.y * 128 + tid;
    const float4* wr = (const float4*)(w + (size_t)n * K);
    float ax = 0.f, ay = 0.f, az = 0.f, aw = 0.f;
    int K4 = K >> 2;
#pragma unroll 8
    for (int k4 = 0; k4 < K4; k4++) {
        float4 wv = wr[k4];
        float4 xv = xr4[k4];
        ax = fmaf(wv.x, xv.x, ax);
        ay = fmaf(wv.y, xv.y, ay);
        az = fmaf(wv.z, xv.z, az);
        aw = fmaf(wv.w, xv.w, aw);
    }
    out[m * N + n] = fmaxf((ax + ay) + (az + aw) + bias[n], 0.f);
}

// ---------------- big dense layers: 128 cols/block, MROWS rows/thread, f32x2 math -------
template<int MROWS, int S>
__global__ void mlp_big_kernel(const float* __restrict__ in, const float* __restrict__ w,
                               const float* __restrict__ bias, const float* __restrict__ bias2,
                               float* __restrict__ out, int K, int N, int do_relu)
{
    __shared__ __align__(16) float xs[32 * S];
    int tid = threadIdx.x;
    int m0 = blockIdx.y * MROWS;
    int n = blockIdx.x * 128 + tid;
    unsigned long long acc2[MROWS / 2];
#pragma unroll
    for (int m = 0; m < MROWS / 2; m++) acc2[m] = 0ull;   // bits of {0.f, 0.f}
    const float* wrow = w + (size_t)n * K;

    for (int k0 = 0; k0 < K; k0 += 32) {
        __syncthreads();
        for (int l = tid; l < MROWS * 32; l += 128) {
            int kk = l & 31, m = l >> 5;
            xs[kk * S + m] = in[(size_t)(m0 + m) * K + k0 + kk];
        }
        __syncthreads();
#pragma unroll 1
        for (int kk4 = 0; kk4 < 8; kk4++) {
            float4 wv = *(const float4*)(wrow + k0 + kk4 * 4);
#pragma unroll
            for (int c = 0; c < 4; c++) {
                float wvc = (c == 0) ? wv.x : (c == 1) ? wv.y : (c == 2) ? wv.z : wv.w;
                unsigned long long wpair;
                asm("mov.b64 %0, {%1, %1};" : "=l"(wpair) : "f"(wvc));
                const ulonglong2* xrow = (const ulonglong2*)(xs + (kk4 * 4 + c) * S);
#pragma unroll
                for (int mq = 0; mq < MROWS / 4; mq++) {
                    ulonglong2 xv = xrow[mq];
                    asm("fma.rn.f32x2 %0, %1, %2, %0;"
                        : "+l"(acc2[2 * mq + 0]) : "l"(xv.x), "l"(wpair));
                    asm("fma.rn.f32x2 %0, %1, %2, %0;"
                        : "+l"(acc2[2 * mq + 1]) : "l"(xv.y), "l"(wpair));
                }
            }
        }
    }
    float bb = bias[n] + (bias2 ? bias2[n] : 0.f);
#pragma unroll
    for (int m = 0; m < MROWS / 2; m++) {
        float lo, hi;
        asm("mov.b64 {%0, %1}, %2;" : "=f"(lo), "=f"(hi) : "l"(acc2[m]));
        float v0 = lo + bb, v1 = hi + bb;
        out[(size_t)(m0 + 2 * m + 0) * N + n] = do_relu ? fmaxf(v0, 0.f) : v0;
        out[(size_t)(m0 + 2 * m + 1) * N + n] = do_relu ? fmaxf(v1, 0.f) : v1;
    }
}

// ---------------- LSTM: one kernel per timestep, fp16 weights ----------------
// Block owns 16 hidden units (64 gate rows). Warp computes 2 rows sharing the
// same h loads. Pointwise update done locally; h double-buffered in global.
__device__ __forceinline__ float sigmoidf_(float x) { return 1.f / (1.f + __expf(-x)); }
__device__ __forceinline__ float tanhf_(float x)    { float e = __expf(2.f * x); return 1.f - 2.f / (e + 1.f); }

__global__ void __launch_bounds__(1024) lstm_step_kernel(const __half* __restrict__ whh,
                                                         float* __restrict__ out, int t)
{
    __shared__ __align__(16) float hs[D128];
    __shared__ float gbuf[64];
    int tid  = threadIdx.x;
    int warp = tid >> 5, lane = tid & 31;
    int u0 = blockIdx.x * 16;

    const float* hin = g_h + (t & 1) * D128;
    for (int k = tid; k < D128; k += 1024) hs[k] = hin[k];
    __syncthreads();

    const float4* h4 = (const float4*)hs;
    // warp handles rows lrA = warp*2 and lrB = warp*2+1, sharing h loads
    int lrA = warp * 2, lrB = lrA + 1;
    int rowA = (lrA >> 4) * D128 + u0 + (lrA & 15);
    int rowB = (lrB >> 4) * D128 + u0 + (lrB & 15);
    const uint4* wrA = (const uint4*)(whh + (size_t)rowA * D128);
    const uint4* wrB = (const uint4*)(whh + (size_t)rowB * D128);

    float ax = 0.f, ay = 0.f, az = 0.f, aw = 0.f;
    float bx = 0.f, by = 0.f, bz = 0.f, bw = 0.f;
#pragma unroll
    for (int it = 0; it < 8; it++) {
        int idx = it * 32 + lane;            // uint4 index: 8 halves each
        uint4 wva = wrA[idx];
        uint4 wvb = wrB[idx];
        float4 ha = h4[idx * 2 + 0];
        float4 hb = h4[idx * 2 + 1];
        float2 a0 = __half22float2(*(__half2*)&wva.x);
        float2 a1 = __half22float2(*(__half2*)&wva.y);
        float2 a2 = __half22float2(*(__half2*)&wva.z);
        float2 a3 = __half22float2(*(__half2*)&wva.w);
        float2 b0 = __half22float2(*(__half2*)&wvb.x);
        float2 b1 = __half22float2(*(__half2*)&wvb.y);
        float2 b2 = __half22float2(*(__half2*)&wvb.z);
        float2 b3 = __half22float2(*(__half2*)&wvb.w);
        ax = fmaf(a0.x, ha.x, ax); ay = fmaf(a0.y, ha.y, ay);
        az = fmaf(a1.x, ha.z, az); aw = fmaf(a1.y, ha.w, aw);
        ax = fmaf(a2.x, hb.x, ax); ay = fmaf(a2.y, hb.y, ay);
        az = fmaf(a3.x, hb.z, az); aw = fmaf(a3.y, hb.w, aw);
        bx = fmaf(b0.x, ha.x, bx); by = fmaf(b0.y, ha.y, by);
        bz = fmaf(b1.x, ha.z, bz); bw = fmaf(b1.y, ha.w, bw);
        bx = fmaf(b2.x, hb.x, bx); by = fmaf(b2.y, hb.y, by);
        bz = fmaf(b3.x, hb.z, bz); bw = fmaf(b3.y, hb.w, bw);
    }
    float sA = (ax + ay) + (az + aw);
    float sB = (bx + by) + (bz + bw);
#pragma unroll
    for (int o = 16; o > 0; o >>= 1) {
        sA += __shfl_down_sync(0xffffffffu, sA, o);
        sB += __shfl_down_sync(0xffffffffu, sB, o);
    }
    if (lane == 0) {
        gbuf[lrA] = sA + g_pre[t * DG + rowA];
        gbuf[lrB] = sB + g_pre[t * DG + rowB];
    }
    __syncthreads();

    if (tid < 16) {
        int u = u0 + tid;
        float ig = gbuf[tid], fg = gbuf[16 + tid], gv = gbuf[32 + tid], og = gbuf[48 + tid];
        float c = sigmoidf_(fg) * g_c[u] + sigmoidf_(ig) * tanhf_(gv);
        float h = sigmoidf_(og) * tanhf_(c);
        g_c[u] = c;
        g_h[((t + 1) & 1) * D128 + u] = h;
        out[t * D128 + u] = h;
    }
}

// ---------------- launch ----------------
extern "C" void kernel_launch(void* const* d_in, const int* in_sizes, int n_in,
                              void* d_out, int out_size)
{
    const float* input = (const float*)d_in[0];
    const float* gc1_w = (const float*)d_in[3];
    const float* gc1_b = (const float*)d_in[4];
    const float* gc2_w = (const float*)d_in[5];
    const float* gc2_b = (const float*)d_in[6];
    const float* fl_w  = (const float*)d_in[7];
    const float* fl_b  = (const float*)d_in[8];
    const float* il_w  = (const float*)d_in[9];
    const float* il_b  = (const float*)d_in[10];
    const float* ol_w  = (const float*)d_in[11];
    const float* ol_b  = (const float*)d_in[12];
    const float* w_ih  = (const float*)d_in[13];
    const float* w_hh  = (const float*)d_in[14];
    const float* b_ih  = (const float*)d_in[15];
    const float* b_hh  = (const float*)d_in[16];
    float* out = (float*)d_out;

    float *px, *pf, *pi, *pz, *ppre;
    __half* pwh;
    cudaGetSymbolAddress((void**)&px,   g_x);
    cudaGetSymbolAddress((void**)&pf,   g_f);
    cudaGetSymbolAddress((void**)&pi,   g_i);
    cudaGetSymbolAddress((void**)&pz,   g_z);
    cudaGetSymbolAddress((void**)&ppre, g_pre);
    cudaGetSymbolAddress((void**)&pwh,  g_whh_h);

    init_kernel<<<2, 1024>>>();
    convert_whh_kernel<<<(4 * D128 * D128) / (8 * 256), 256>>>(w_hh, pwh);
    gcn_kernel<<<BATCH, 1024>>>(input, gc1_w, gc1_b, gc2_w, gc2_b, px);
    // f = relu(x @ fl_w^T + fl_b)         (K=1024, N=256)
    mlp_small_kernel<<<dim3(BATCH, D16 / 128), 128>>>(px, fl_w, fl_b, pf, NPTS, D16);
    // i = relu(f @ il_w^T + il_b)         (K=256, N=1024)
    mlp_small_kernel<<<dim3(BATCH, D64 / 128), 128>>>(pf, il_w, il_b, pi, D16, D64);
    // z = relu(i @ ol_w^T + ol_b)         (K=1024, N=2048)
    mlp_big_kernel<4, 8><<<dim3(D128 / 128, BATCH / 4), 128>>>(pi, ol_w, ol_b, nullptr, pz, D64, D128, 1);
    // pre = z @ w_ih^T + b_ih + b_hh      (K=2048, N=8192)
    mlp_big_kernel<16, 24><<<dim3(DG / 128, BATCH / 16), 128>>>(pz, w_ih, b_ih, b_hh, ppre, D128, DG, 0);
    // LSTM scan: 64 sequential step kernels (graph-serialized)
    for (int t = 0; t < BATCH; t++)
        lstm_step_kernel<<<D128 / 16, 1024>>>(pwh, out, t);
}